// round 15
// baseline (speedup 1.0000x reference)
#include <cuda_runtime.h>
#include <cuda_fp16.h>
#include <cstdint>
#include <math.h>

// ---------------- fixed problem structure ----------------
#define TT      50
#define BRANCH  4
#define D_IN    384
#define HH      512
#define G3      1536
#define MAXB    2000
#define NPAR    13
#define NNODE   (MAXB * TT)

// ---------------- device scratch ----------------
__device__ __half g_c    [(size_t)NNODE * HH];
__device__ __half g_xwf  [(size_t)MAXB * NPAR * HH];
__device__ __half g_fcsum[(size_t)MAXB * 16 * HH];
__device__ __half g_e16  [(size_t)NNODE * D_IN];
__device__ __half g_h16  [(size_t)NNODE * HH];
__device__ __half g_hsum16[(size_t)MAXB * 16 * HH];
__device__ __half g_Wt_iou[G3 * D_IN];   // fp16, K-major [N'][K], gate-interleaved N'
__device__ __half g_Ut_iou[G3 * HH];     // gate-interleaved N'
__device__ __half g_Wt_f  [HH * D_IN];
__device__ __half g_Ut_f  [HH * HH];

// ---------------- PTX helpers (portable ISA: sm_80-level) ----------------
__device__ __forceinline__ uint32_t s2u(const void* p) {
    uint32_t a;
    asm("{ .reg .u64 t; cvta.to.shared.u64 t, %1; cvt.u32.u64 %0, t; }" : "=r"(a) : "l"(p));
    return a;
}
__device__ __forceinline__ void cpasync16(uint32_t dst, const void* src) {
    asm volatile("cp.async.cg.shared.global [%0], [%1], 16;" :: "r"(dst), "l"(src));
}
__device__ __forceinline__ void cpcommit() {
    asm volatile("cp.async.commit_group;" ::: "memory");
}
template<int N>
__device__ __forceinline__ void cpwait() {
    asm volatile("cp.async.wait_group %0;" :: "n"(N) : "memory");
}
__device__ __forceinline__ void ldsm4(uint32_t& r0, uint32_t& r1, uint32_t& r2, uint32_t& r3,
                                      uint32_t a) {
    asm volatile("ldmatrix.sync.aligned.m8n8.x4.shared.b16 {%0,%1,%2,%3}, [%4];"
                 : "=r"(r0), "=r"(r1), "=r"(r2), "=r"(r3) : "r"(a));
}
__device__ __forceinline__ void mma16816(float* c,
                                         uint32_t a0, uint32_t a1, uint32_t a2, uint32_t a3,
                                         uint32_t b0, uint32_t b1) {
    asm volatile(
        "mma.sync.aligned.m16n8k16.row.col.f32.f16.f16.f32 "
        "{%0,%1,%2,%3}, {%4,%5,%6,%7}, {%8,%9}, {%0,%1,%2,%3};"
        : "+f"(c[0]), "+f"(c[1]), "+f"(c[2]), "+f"(c[3])
        : "r"(a0), "r"(a1), "r"(a2), "r"(a3), "r"(b0), "r"(b1));
}
__device__ __forceinline__ float tanh_fast(float x) {
    float r;
    asm("tanh.approx.f32 %0, %1;" : "=f"(r) : "f"(x));
    return r;
}
__device__ __forceinline__ float sigmoid_fast(float x) {
    return fmaf(tanh_fast(0.5f * x), 0.5f, 0.5f);
}

// ---------------- GEMM tiling ----------------
#define BK     32                      // halves per k-chunk
#define ROWB   80                      // smem row stride (bytes)

// All modes: 128xNT CTA tile, 8 warps as 4M x 2N (warp tile 32 x NT/2),
// register double-buffered fragments, per-chunk cp.async barrier.
// MODE 0: xwf16 = acc + bias (fp16 out)            (NT=128, 4 stg)
// MODE 1: fc = sigmoid(acc + xwf16[parent]) * c[child];
//         fcsum + hsum over 4 children via shfl    (NT=128, 4 stg)
// MODE 2: fused LSTM cell, gate-interleaved cols   (NT=96, 5 stg)
template<int MODE>
__global__ void __launch_bounds__(256, 2)
hgemm(const __half* __restrict__ A,  const __half* __restrict__ B1, int K1, int strideA,
      const __half* __restrict__ A2, const __half* __restrict__ B2, int K2,
      const float* __restrict__ bias, const __half* __restrict__ xwf,
      const __half* __restrict__ cbuf,
      __half* __restrict__ cout, __half* __restrict__ h16out,
      const __half* __restrict__ fcsum, __half* __restrict__ fcsum_out,
      __half* __restrict__ hsum_out,
      int M, int Nw, int lstart, int lcnt, int lvalid, int pcnt)
{
    constexpr int THREADS = 256;
    constexpr int ST   = (MODE == 2) ? 5 : 4;     // pipeline stages
    constexpr int MT   = 128;
    constexpr int NT   = (MODE == 2) ? 96 : 128;
    constexpr int WMT  = 32;                      // warp tile M (warps 4x2)
    constexpr int WNT  = NT / 2;                  // 48 / 64
    constexpr int MI   = 2;                       // WMT/16
    constexpr int NJ   = WNT / 8;                 // 6 / 8
    constexpr int NLD4 = WNT / 16;                // 3 / 4
    constexpr int ASTG = MT * ROWB;
    constexpr int BSTG = NT * ROWB;
    constexpr int NBL  = (NT * 4 + THREADS - 1) / THREADS;

    extern __shared__ char smraw[];
    const uint32_t sb  = s2u(smraw);
    const uint32_t sbB = sb + ST * ASTG;

    const int tid  = threadIdx.x;
    const int lane = tid & 31;
    const int wid  = tid >> 5;
    const int wm   = wid >> 1;
    const int wn   = wid & 1;
    const int bm   = blockIdx.y * MT;
    const int bn   = blockIdx.x * NT;

    // ---- A loader: 2 gathered (row, 16B-chunk) slots per thread ----
    const __half* a1p[2];
    const __half* a2p[2];
    uint32_t asf[2];
    #pragma unroll
    for (int t = 0; t < 2; t++) {
        const int idx = tid + t * THREADS;
        int r = bm + (idx >> 2); if (r >= M) r = M - 1;
        int o = r % lcnt; if (o >= lvalid) o = lvalid - 1;
        const int tr = r / lcnt, lc = lstart + o;
        const int ch = idx & 3;
        a1p[t] = A + (size_t)(tr * TT + lc) * strideA + ch * 8;
        a2p[t] = (K2 > 0) ? A2 + (size_t)r * K2 + ch * 8 : nullptr;
        asf[t] = (uint32_t)((idx >> 2) * ROWB + ch * 16);
    }

    // ---- B loader ----
    const __half* pb1[NBL];
    const __half* pb2[NBL];
    uint32_t bso[NBL];
    bool bok[NBL];
    #pragma unroll
    for (int i = 0; i < NBL; i++) {
        const int idx = tid + i * THREADS;
        bok[i] = idx < NT * 4;
        const int row = bok[i] ? (idx >> 2) : 0;
        const int ch  = idx & 3;
        pb1[i] = B1 + (size_t)(bn + row) * K1 + ch * 8;
        pb2[i] = (K2 > 0) ? B2 + (size_t)(bn + row) * K2 + ch * 8 : nullptr;
        bso[i] = (uint32_t)(row * ROWB + ch * 16);
    }

    const int n1 = K1 / BK, n2 = (K2 > 0) ? K2 / BK : 0, nt = n1 + n2;

    auto issue = [&](int ci, int s) {
        const bool p2 = (ci >= n1);
        const int  kb = (p2 ? (ci - n1) : ci) * BK;
        const uint32_t abase = sb  + s * ASTG;
        const uint32_t bbase = sbB + s * BSTG;
        #pragma unroll
        for (int t = 0; t < 2; t++)
            cpasync16(abase + asf[t], (p2 ? a2p[t] : a1p[t]) + kb);
        #pragma unroll
        for (int i = 0; i < NBL; i++)
            if (bok[i]) cpasync16(bbase + bso[i], (p2 ? pb2[i] : pb1[i]) + kb);
    };

    // ---- ldmatrix offsets ----
    const int rl = (lane & 7) + ((lane >> 3) & 1) * 8;
    const int kq = (lane >> 4) * 16;
    uint32_t aoff[MI];
    #pragma unroll
    for (int i = 0; i < MI; i++)
        aoff[i] = (uint32_t)((wm * WMT + i * 16 + rl) * ROWB + kq);
    const int nl  = (lane & 7) + (lane >> 4) * 8;
    const int kb2 = ((lane >> 3) & 1) * 16;
    uint32_t boff4[NLD4];
    #pragma unroll
    for (int p = 0; p < NLD4; p++)
        boff4[p] = (uint32_t)((wn * WNT + p * 16 + nl) * ROWB + kb2);

    float acc[MI][NJ][4];
    #pragma unroll
    for (int i = 0; i < MI; i++)
        #pragma unroll
        for (int j = 0; j < NJ; j++)
            #pragma unroll
            for (int q = 0; q < 4; q++) acc[i][j][q] = 0.f;

    #pragma unroll
    for (int s = 0; s < ST - 1; s++) { issue(s, s); cpcommit(); }

    {
        // ---- software-pipelined fragments: double-buffered regs (all modes) ----
        uint32_t af[2][MI][4], b0f[2][NJ], b1f[2][NJ];
        auto lf = [&](int buf, uint32_t as, uint32_t bs, int ks) {
            #pragma unroll
            for (int i = 0; i < MI; i++)
                ldsm4(af[buf][i][0], af[buf][i][1], af[buf][i][2], af[buf][i][3],
                      as + aoff[i] + ks * 32);
            #pragma unroll
            for (int p = 0; p < NLD4; p++) {
                uint32_t t0, t1, t2, t3;
                ldsm4(t0, t1, t2, t3, bs + boff4[p] + ks * 32);
                b0f[buf][2 * p] = t0;     b1f[buf][2 * p] = t1;
                b0f[buf][2 * p + 1] = t2; b1f[buf][2 * p + 1] = t3;
            }
        };
        auto mm = [&](int buf) {
            #pragma unroll
            for (int i = 0; i < MI; i++)
                #pragma unroll
                for (int j = 0; j < NJ; j++)
                    mma16816(acc[i][j], af[buf][i][0], af[buf][i][1],
                             af[buf][i][2], af[buf][i][3], b0f[buf][j], b1f[buf][j]);
        };

        cpwait<ST - 2>();
        __syncthreads();
        lf(0, sb, sbB, 0);

        for (int ci = 0; ci < nt; ci++) {
            const uint32_t as = sb  + (ci % ST) * ASTG;
            const uint32_t bs = sbB + (ci % ST) * BSTG;
            const int pre = ci + ST - 1;
            if (pre < nt) issue(pre, pre % ST);
            cpcommit();
            lf(1, as, bs, 1);          // ks=1 frags load behind ks=0 MMAs
            mm(0);
            cpwait<ST - 2>();          // chunk ci+1 stage complete
            __syncthreads();
            if (ci + 1 < nt)
                lf(0, sb + ((ci + 1) % ST) * ASTG,
                       sbB + ((ci + 1) % ST) * BSTG, 0);
            mm(1);
        }
    }

    // ---- epilogue ----
    const int g  = lane >> 2;
    const int cq = (lane & 3) * 2;
    #pragma unroll
    for (int mi = 0; mi < MI; mi++) {
        #pragma unroll
        for (int half = 0; half < 2; half++) {
            const int row = bm + wm * WMT + mi * 16 + half * 8 + g;
            const int h2 = half * 2;

            if (MODE == 1) {
                // fused fc + h: 4-child fcsum/hsum reduction (no early-exit: shfl
                // needs all lanes; child quads align with shfl quads since lcnt%4==0)
                const int rc   = (row < M) ? row : M - 1;
                const int t    = rc / lcnt;
                const int off  = rc % lcnt;
                const bool valid = (row < M) && (off < lvalid);
                const int loc  = lstart + ((off < lvalid) ? off : 0);
                const __half* xrow = xwf + (size_t)(t * NPAR + (loc - 1) / BRANCH) * HH;
                const size_t gnr = (size_t)(t * TT + loc) * HH;
                const __half* crow = cbuf + gnr;
                const __half* hrow = A + gnr;          // A == h16, strideA == HH
                float redf[NJ][2], redh[NJ][2];
                #pragma unroll
                for (int nj = 0; nj < NJ; nj++) {
                    const int col = bn + wn * WNT + nj * 8 + cq;
                    float2 xr = __half22float2(*(const __half2*)(xrow + col));
                    float2 cr = __half22float2(*(const __half2*)(crow + col));
                    float2 hr = __half22float2(*(const __half2*)(hrow + col));
                    float v0 = sigmoid_fast(acc[mi][nj][h2]     + xr.x) * cr.x;
                    float v1 = sigmoid_fast(acc[mi][nj][h2 + 1] + xr.y) * cr.y;
                    float w0 = hr.x, w1 = hr.y;
                    if (!valid) { v0 = 0.f; v1 = 0.f; w0 = 0.f; w1 = 0.f; }
                    v0 += __shfl_xor_sync(0xffffffffu, v0, 4);
                    v0 += __shfl_xor_sync(0xffffffffu, v0, 8);
                    v1 += __shfl_xor_sync(0xffffffffu, v1, 4);
                    v1 += __shfl_xor_sync(0xffffffffu, v1, 8);
                    w0 += __shfl_xor_sync(0xffffffffu, w0, 4);
                    w0 += __shfl_xor_sync(0xffffffffu, w0, 8);
                    w1 += __shfl_xor_sync(0xffffffffu, w1, 4);
                    w1 += __shfl_xor_sync(0xffffffffu, w1, 8);
                    redf[nj][0] = v0; redf[nj][1] = v1;
                    redh[nj][0] = w0; redh[nj][1] = w1;
                }
                if ((lane & 12) == 0 && valid) {
                    const size_t pr = (size_t)(t * pcnt + (off >> 2)) * HH;
                    #pragma unroll
                    for (int nj = 0; nj < NJ; nj++) {
                        const int col = bn + wn * WNT + nj * 8 + cq;
                        *(__half2*)(fcsum_out + pr + col) = __floats2half2_rn(redf[nj][0], redf[nj][1]);
                        *(__half2*)(hsum_out + pr + col) = __floats2half2_rn(redh[nj][0], redh[nj][1]);
                    }
                }
            } else if (MODE == 2) {
                if (row >= M) continue;
                const int t = row / lcnt, loc = lstart + row % lcnt;
                const size_t gn = (size_t)(t * TT + loc) * HH;
                #pragma unroll
                for (int b = 0; b < NJ / 3; b++) {
                    const int hc = blockIdx.x * 32 + wn * 16 + b * 8 + cq;
                    float fs0 = 0.f, fs1 = 0.f;
                    if (fcsum) {
                        float2 f = __half22float2(*(const __half2*)(fcsum + (size_t)row * HH + hc));
                        fs0 = f.x; fs1 = f.y;
                    }
                    float iv0 = acc[mi][b * 3 + 0][h2]     + bias[hc];
                    float iv1 = acc[mi][b * 3 + 0][h2 + 1] + bias[hc + 1];
                    float ov0 = acc[mi][b * 3 + 1][h2]     + bias[HH + hc];
                    float ov1 = acc[mi][b * 3 + 1][h2 + 1] + bias[HH + hc + 1];
                    float uv0 = acc[mi][b * 3 + 2][h2]     + bias[2 * HH + hc];
                    float uv1 = acc[mi][b * 3 + 2][h2 + 1] + bias[2 * HH + hc + 1];
                    float cn0 = sigmoid_fast(iv0) * tanh_fast(uv0) + fs0;
                    float cn1 = sigmoid_fast(iv1) * tanh_fast(uv1) + fs1;
                    float hn0 = sigmoid_fast(ov0) * tanh_fast(cn0);
                    float hn1 = sigmoid_fast(ov1) * tanh_fast(cn1);
                    *(__half2*)(cout + gn + hc)   = __floats2half2_rn(cn0, cn1);
                    *(__half2*)(h16out + gn + hc) = __floats2half2_rn(hn0, hn1);
                }
            } else {
                if (row >= M) continue;
                __half* orow = h16out + (size_t)row * Nw;   // MODE0: fp16 output
                #pragma unroll
                for (int nj = 0; nj < NJ; nj++) {
                    const int col = bn + wn * WNT + nj * 8 + cq;
                    float2 bb = *(const float2*)(bias + col);
                    *(__half2*)(orow + col) =
                        __floats2half2_rn(acc[mi][nj][h2] + bb.x, acc[mi][nj][h2 + 1] + bb.y);
                }
            }
        }
    }
}

// ---------------- fp32 -> fp16 cast (float4-vectorized) ----------------
__global__ void cvt16(const float* __restrict__ in, __half* __restrict__ o, int n4) {
    for (int i = blockIdx.x * blockDim.x + threadIdx.x; i < n4;
         i += gridDim.x * blockDim.x) {
        float4 v = ((const float4*)in)[i];
        __half2 a = __floats2half2_rn(v.x, v.y);
        __half2 b = __floats2half2_rn(v.z, v.w);
        ((__half2*)o)[2 * i]     = a;
        ((__half2*)o)[2 * i + 1] = b;
    }
}

// ---------------- weight transpose + fp16 (+optional gate-interleave permute) --------
template<int PERM>
__global__ void wtrans16(const float* __restrict__ W, __half* __restrict__ Wt,
                         int K, int N)
{
    __shared__ float t[32][33];
    const int bx = blockIdx.x * 32;
    const int by = blockIdx.y * 32;
    const int x = threadIdx.x, y = threadIdx.y;
    #pragma unroll
    for (int i = 0; i < 32; i += 8)
        t[y + i][x] = W[(size_t)(by + y + i) * N + bx + x];
    __syncthreads();
    #pragma unroll
    for (int i = 0; i < 32; i += 8) {
        int n = bx + y + i;
        int np = n;
        if (PERM) {
            int gg = n / HH, Hc = n % HH;
            np = (Hc / 8) * 24 + gg * 8 + (Hc % 8);
        }
        Wt[(size_t)np * K + by + x] = __float2half(t[x][y + i]);
    }
}

// ---------------- zero-fill hsum/fcsum rows for childless level-2 parents ------------
__global__ void tl_zfill(__half* __restrict__ hsum16, __half* __restrict__ fcsum,
                         int B, int Poff, int Pcnt, int Pfill)
{
    int total = B * Pfill * HH;
    for (int idx = blockIdx.x * blockDim.x + threadIdx.x; idx < total;
         idx += gridDim.x * blockDim.x) {
        int n = idx & (HH - 1);
        int pr = idx >> 9;
        int t = pr / Pfill;
        int p = Poff + pr % Pfill;
        size_t a = (size_t)(t * Pcnt + p) * HH + n;
        hsum16[a] = __float2half(0.f);
        fcsum[a]  = __float2half(0.f);
    }
}

// ---------------- readout (accurate tanh: directly output-facing) ----------------
__global__ void tl_readout(const __half* __restrict__ h16, float* __restrict__ out, int B)
{
    int g = blockIdx.x;
    for (int n = threadIdx.x; n < HH; n += blockDim.x) {
        const __half* hp = h16 + (size_t)g * TT * HH + n;
        float s = 0.f;
        #pragma unroll
        for (int tn = 0; tn < TT; tn++) s += __half2float(hp[(size_t)tn * HH]);
        if (n < 256) out[(size_t)g * 256 + n] = s;
        else out[(size_t)B * 256 + (size_t)g * 256 + (n - 256)] = tanhf(s);
    }
}

// ---------------- launch ----------------
extern "C" void kernel_launch(void* const* d_in, const int* in_sizes, int n_in,
                              void* d_out, int out_size)
{
    const float* embed = (const float*)d_in[0];
    const float* W_iou = (const float*)d_in[1];
    const float* U_iou = (const float*)d_in[2];
    const float* b_iou = (const float*)d_in[3];
    const float* W_f   = (const float*)d_in[4];
    const float* U_f   = (const float*)d_in[5];
    const float* b_f   = (const float*)d_in[6];

    int N = in_sizes[0] / D_IN;
    int B = N / TT;
    if (B > MAXB) B = MAXB;

    __half *c, *xwf, *fcsum, *e16, *h16, *hsum16, *Wt_iou, *Ut_iou, *Wt_f, *Ut_f;
    cudaGetSymbolAddress((void**)&c,      g_c);
    cudaGetSymbolAddress((void**)&xwf,    g_xwf);
    cudaGetSymbolAddress((void**)&fcsum,  g_fcsum);
    cudaGetSymbolAddress((void**)&e16,    g_e16);
    cudaGetSymbolAddress((void**)&h16,    g_h16);
    cudaGetSymbolAddress((void**)&hsum16, g_hsum16);
    cudaGetSymbolAddress((void**)&Wt_iou, g_Wt_iou);
    cudaGetSymbolAddress((void**)&Ut_iou, g_Ut_iou);
    cudaGetSymbolAddress((void**)&Wt_f,   g_Wt_f);
    cudaGetSymbolAddress((void**)&Ut_f,   g_Ut_f);

    const int SM01 = 4 * (128 * ROWB + 128 * ROWB);   // 81920  (2 CTAs/SM)
    const int SM2  = 5 * (128 * ROWB + 96 * ROWB);    // 89600  (2 CTAs/SM)
    cudaFuncSetAttribute(hgemm<0>, cudaFuncAttributeMaxDynamicSharedMemorySize, SM01);
    cudaFuncSetAttribute(hgemm<1>, cudaFuncAttributeMaxDynamicSharedMemorySize, SM01);
    cudaFuncSetAttribute(hgemm<2>, cudaFuncAttributeMaxDynamicSharedMemorySize, SM2);

    dim3 tb(32, 8);
    cvt16<<<4096, 256>>>(embed, e16, B * TT * D_IN / 4);                       // 1
    wtrans16<1><<<dim3(G3 / 32, D_IN / 32), tb>>>(W_iou, Wt_iou, D_IN, G3);    // 2
    wtrans16<0><<<dim3(HH / 32, D_IN / 32), tb>>>(W_f,   Wt_f,   D_IN, HH);    // 3

    #define GY(M) (((M) + 127) / 128)

    // 4: level 3 (deepest): fused gates+cell, no children  [ncu sample target]
    hgemm<2><<<dim3(G3 / 96, GY(B * 29)), 256, SM2>>>(
        e16, Wt_iou, D_IN, D_IN, nullptr, nullptr, 0,
        b_iou, nullptr, nullptr, c, h16, nullptr, nullptr, nullptr,
        B * 29, G3, 21, 29, 29, 0);

    // 5: xwf (fp16) for parent-capable nodes (locals 0..12)
    hgemm<0><<<dim3(HH / 128, GY(B * NPAR)), 256, SM01>>>(
        e16, Wt_f, D_IN, D_IN, nullptr, nullptr, 0,
        b_f, nullptr, nullptr, nullptr, xwf, nullptr, nullptr, nullptr,
        B * NPAR, HH, 0, NPAR, NPAR, 0);

    wtrans16<1><<<dim3(G3 / 32, HH / 32), tb>>>(U_iou, Ut_iou, HH, G3);        // 6
    wtrans16<0><<<dim3(HH / 32, HH / 32), tb>>>(U_f,   Ut_f,   HH, HH);        // 7

    // zero hsum/fcsum for level-2 childless parents (locals 13..20 -> offs 8..15)
    tl_zfill<<<512, 256>>>(hsum16, fcsum, B, 8, 16, 8);                        // 8

    // {Pstart, Pcnt, Cstart, CcntPad, CcntValid}
    const int lp[3][5] = { {5, 16, 21, 32, 29}, {1, 4, 5, 16, 16}, {0, 1, 1, 4, 4} };
    for (int li = 0; li < 3; li++) {
        int Pstart = lp[li][0], Pcnt = lp[li][1], Cstart = lp[li][2];
        int Cpad = lp[li][3], Cval = lp[li][4];

        // fc = sigmoid(h_child @ U_f + xwf[parent]) * c_child;
        // fcsum (fp16) + hsum (fp16) fused via shfl over the 4-child quad
        hgemm<1><<<dim3(HH / 128, GY(B * Cpad)), 256, SM01>>>(
            h16, Ut_f, HH, HH, nullptr, nullptr, 0,
            nullptr, xwf, c, nullptr, nullptr, nullptr, fcsum, hsum16,
            B * Cpad, HH, Cstart, Cpad, Cval, Pcnt);

        // fused: gates = E@W_iou + hsum@U_iou + b  ->  cell  -> h16, c
        hgemm<2><<<dim3(G3 / 96, GY(B * Pcnt)), 256, SM2>>>(
            e16, Wt_iou, D_IN, D_IN, hsum16, Ut_iou, HH,
            b_iou, nullptr, nullptr, c, h16, fcsum, nullptr, nullptr,
            B * Pcnt, G3, Pstart, Pcnt, Pcnt, 0);
    }

    tl_readout<<<B, 256>>>(h16, (float*)d_out, B);
    #undef GY
}

// round 16
// speedup vs baseline: 1.0238x; 1.0238x over previous
#include <cuda_runtime.h>
#include <cuda_fp16.h>
#include <cstdint>
#include <math.h>

// ---------------- fixed problem structure ----------------
#define TT      50
#define BRANCH  4
#define D_IN    384
#define HH      512
#define G3      1536
#define MAXB    2000
#define NPAR    13
#define NNODE   (MAXB * TT)

// ---------------- device scratch ----------------
__device__ __half g_c    [(size_t)NNODE * HH];
__device__ __half g_xwf  [(size_t)MAXB * NPAR * HH];
__device__ __half g_fcsum[(size_t)MAXB * 16 * HH];
__device__ __half g_e16  [(size_t)NNODE * D_IN];
__device__ __half g_h16  [(size_t)NNODE * HH];
__device__ __half g_hsum16[(size_t)MAXB * 16 * HH];
__device__ __half g_Wt_iou[G3 * D_IN];   // fp16, K-major [N'][K], gate-interleaved N'
__device__ __half g_Ut_iou[G3 * HH];     // gate-interleaved N'
__device__ __half g_Wt_f  [HH * D_IN];
__device__ __half g_Ut_f  [HH * HH];

// ---------------- PTX helpers (portable ISA: sm_80-level) ----------------
__device__ __forceinline__ uint32_t s2u(const void* p) {
    uint32_t a;
    asm("{ .reg .u64 t; cvta.to.shared.u64 t, %1; cvt.u32.u64 %0, t; }" : "=r"(a) : "l"(p));
    return a;
}
__device__ __forceinline__ void cpasync16(uint32_t dst, const void* src) {
    asm volatile("cp.async.cg.shared.global [%0], [%1], 16;" :: "r"(dst), "l"(src));
}
__device__ __forceinline__ void cpcommit() {
    asm volatile("cp.async.commit_group;" ::: "memory");
}
template<int N>
__device__ __forceinline__ void cpwait() {
    asm volatile("cp.async.wait_group %0;" :: "n"(N) : "memory");
}
__device__ __forceinline__ void ldsm4(uint32_t& r0, uint32_t& r1, uint32_t& r2, uint32_t& r3,
                                      uint32_t a) {
    asm volatile("ldmatrix.sync.aligned.m8n8.x4.shared.b16 {%0,%1,%2,%3}, [%4];"
                 : "=r"(r0), "=r"(r1), "=r"(r2), "=r"(r3) : "r"(a));
}
__device__ __forceinline__ void mma16816(float* c,
                                         uint32_t a0, uint32_t a1, uint32_t a2, uint32_t a3,
                                         uint32_t b0, uint32_t b1) {
    asm volatile(
        "mma.sync.aligned.m16n8k16.row.col.f32.f16.f16.f32 "
        "{%0,%1,%2,%3}, {%4,%5,%6,%7}, {%8,%9}, {%0,%1,%2,%3};"
        : "+f"(c[0]), "+f"(c[1]), "+f"(c[2]), "+f"(c[3])
        : "r"(a0), "r"(a1), "r"(a2), "r"(a3), "r"(b0), "r"(b1));
}
__device__ __forceinline__ float tanh_fast(float x) {
    float r;
    asm("tanh.approx.f32 %0, %1;" : "=f"(r) : "f"(x));
    return r;
}
__device__ __forceinline__ float sigmoid_fast(float x) {
    return fmaf(tanh_fast(0.5f * x), 0.5f, 0.5f);
}

// ---------------- GEMM tiling ----------------
#define BK     32                      // halves per k-chunk
#define ROWB   80                      // smem row stride (bytes)

// MODE 0: xwf16 = acc + bias (fp16 out)                    (128x128, warps 2x4, 4 stg)
// MODE 1: fc = sigmoid(acc + xwf16[parent]) * c[child];
//         fcsum + hsum over 4 children via shfl            (128x128, warps 2x4, 4 stg)
// MODE 2: fused LSTM cell, gate-interleaved cols           (128x96, warps 4x2, 32x48, 5 stg)
template<int MODE>
__global__ void __launch_bounds__(256, 2)
hgemm(const __half* __restrict__ A,  const __half* __restrict__ B1, int K1, int strideA,
      const __half* __restrict__ A2, const __half* __restrict__ B2, int K2,
      const float* __restrict__ bias, const __half* __restrict__ xwf,
      const __half* __restrict__ cbuf,
      __half* __restrict__ cout, __half* __restrict__ h16out,
      const __half* __restrict__ fcsum, __half* __restrict__ fcsum_out,
      __half* __restrict__ hsum_out,
      int M, int Nw, int lstart, int lcnt, int lvalid, int pcnt)
{
    constexpr int THREADS = 256;
    constexpr int ST   = (MODE == 2) ? 5 : 4;     // pipeline stages
    constexpr int MT   = 128;
    constexpr int NT   = (MODE == 2) ? 96 : 128;
    constexpr int WMW  = (MODE == 2) ? 4 : 2;     // warps along M
    constexpr int WMT  = MT / WMW;                // 32 / 64
    constexpr int WNT  = NT / (8 / WMW);          // 48 / 32
    constexpr int MI   = WMT / 16;                // 2 / 4
    constexpr int NJ   = WNT / 8;                 // 6 / 4
    constexpr int NLD4 = WNT / 16;                // 3 / 2
    constexpr int ASTG = MT * ROWB;
    constexpr int BSTG = NT * ROWB;
    constexpr int NBL  = (NT * 4 + THREADS - 1) / THREADS;

    extern __shared__ char smraw[];
    const uint32_t sb  = s2u(smraw);
    const uint32_t sbB = sb + ST * ASTG;

    const int tid  = threadIdx.x;
    const int lane = tid & 31;
    const int wid  = tid >> 5;
    const int wm   = (MODE == 2) ? (wid >> 1) : (wid >> 2);
    const int wn   = (MODE == 2) ? (wid & 1)  : (wid & 3);
    const int bm   = blockIdx.y * MT;
    const int bn   = blockIdx.x * NT;

    // ---- A loader: 2 gathered (row, 16B-chunk) slots per thread ----
    const __half* a1p[2];
    const __half* a2p[2];
    uint32_t asf[2];
    #pragma unroll
    for (int t = 0; t < 2; t++) {
        const int idx = tid + t * THREADS;
        int r = bm + (idx >> 2); if (r >= M) r = M - 1;
        int o = r % lcnt; if (o >= lvalid) o = lvalid - 1;
        const int tr = r / lcnt, lc = lstart + o;
        const int ch = idx & 3;
        a1p[t] = A + (size_t)(tr * TT + lc) * strideA + ch * 8;
        a2p[t] = (K2 > 0) ? A2 + (size_t)r * K2 + ch * 8 : nullptr;
        asf[t] = (uint32_t)((idx >> 2) * ROWB + ch * 16);
    }

    // ---- B loader ----
    const __half* pb1[NBL];
    const __half* pb2[NBL];
    uint32_t bso[NBL];
    bool bok[NBL];
    #pragma unroll
    for (int i = 0; i < NBL; i++) {
        const int idx = tid + i * THREADS;
        bok[i] = idx < NT * 4;
        const int row = bok[i] ? (idx >> 2) : 0;
        const int ch  = idx & 3;
        pb1[i] = B1 + (size_t)(bn + row) * K1 + ch * 8;
        pb2[i] = (K2 > 0) ? B2 + (size_t)(bn + row) * K2 + ch * 8 : nullptr;
        bso[i] = (uint32_t)(row * ROWB + ch * 16);
    }

    const int n1 = K1 / BK, n2 = (K2 > 0) ? K2 / BK : 0, nt = n1 + n2;

    auto issue = [&](int ci, int s) {
        const bool p2 = (ci >= n1);
        const int  kb = (p2 ? (ci - n1) : ci) * BK;
        const uint32_t abase = sb  + s * ASTG;
        const uint32_t bbase = sbB + s * BSTG;
        #pragma unroll
        for (int t = 0; t < 2; t++)
            cpasync16(abase + asf[t], (p2 ? a2p[t] : a1p[t]) + kb);
        #pragma unroll
        for (int i = 0; i < NBL; i++)
            if (bok[i]) cpasync16(bbase + bso[i], (p2 ? pb2[i] : pb1[i]) + kb);
    };

    // ---- ldmatrix offsets ----
    const int rl = (lane & 7) + ((lane >> 3) & 1) * 8;
    const int kq = (lane >> 4) * 16;
    uint32_t aoff[MI];
    #pragma unroll
    for (int i = 0; i < MI; i++)
        aoff[i] = (uint32_t)((wm * WMT + i * 16 + rl) * ROWB + kq);
    const int nl  = (lane & 7) + (lane >> 4) * 8;
    const int kb2 = ((lane >> 3) & 1) * 16;
    uint32_t boff4[NLD4];
    #pragma unroll
    for (int p = 0; p < NLD4; p++)
        boff4[p] = (uint32_t)((wn * WNT + p * 16 + nl) * ROWB + kb2);

    float acc[MI][NJ][4];
    #pragma unroll
    for (int i = 0; i < MI; i++)
        #pragma unroll
        for (int j = 0; j < NJ; j++)
            #pragma unroll
            for (int q = 0; q < 4; q++) acc[i][j][q] = 0.f;

    #pragma unroll
    for (int s = 0; s < ST - 1; s++) { issue(s, s); cpcommit(); }

    if constexpr (MODE == 2) {
        // ---- software-pipelined fragments: double-buffered regs ----
        uint32_t af[2][MI][4], b0f[2][NJ], b1f[2][NJ];
        auto lf = [&](int buf, uint32_t as, uint32_t bs, int ks) {
            #pragma unroll
            for (int i = 0; i < MI; i++)
                ldsm4(af[buf][i][0], af[buf][i][1], af[buf][i][2], af[buf][i][3],
                      as + aoff[i] + ks * 32);
            #pragma unroll
            for (int p = 0; p < NLD4; p++) {
                uint32_t t0, t1, t2, t3;
                ldsm4(t0, t1, t2, t3, bs + boff4[p] + ks * 32);
                b0f[buf][2 * p] = t0;     b1f[buf][2 * p] = t1;
                b0f[buf][2 * p + 1] = t2; b1f[buf][2 * p + 1] = t3;
            }
        };
        auto mm = [&](int buf) {
            #pragma unroll
            for (int i = 0; i < MI; i++)
                #pragma unroll
                for (int j = 0; j < NJ; j++)
                    mma16816(acc[i][j], af[buf][i][0], af[buf][i][1],
                             af[buf][i][2], af[buf][i][3], b0f[buf][j], b1f[buf][j]);
        };

        cpwait<ST - 2>();
        __syncthreads();
        lf(0, sb, sbB, 0);

        for (int ci = 0; ci < nt; ci++) {
            const uint32_t as = sb  + (ci % ST) * ASTG;
            const uint32_t bs = sbB + (ci % ST) * BSTG;
            const int pre = ci + ST - 1;
            if (pre < nt) issue(pre, pre % ST);
            cpcommit();
            lf(1, as, bs, 1);          // ks=1 frags load behind ks=0 MMAs
            mm(0);
            cpwait<ST - 2>();          // chunk ci+1 stage complete
            __syncthreads();
            if (ci + 1 < nt)
                lf(0, sb + ((ci + 1) % ST) * ASTG,
                       sbB + ((ci + 1) % ST) * BSTG, 0);
            mm(1);
        }
    } else {
        for (int ci = 0; ci < nt; ci++) {
            cpwait<ST - 2>();
            __syncthreads();

            const int pre = ci + ST - 1;
            if (pre < nt) issue(pre, pre % ST);
            cpcommit();

            const uint32_t as = sb  + (ci % ST) * ASTG;
            const uint32_t bs = sbB + (ci % ST) * BSTG;

            #pragma unroll
            for (int ks = 0; ks < 2; ks++) {
                uint32_t af[MI][4];
                uint32_t br0[NJ], br1[NJ];
                #pragma unroll
                for (int i = 0; i < MI; i++)
                    ldsm4(af[i][0], af[i][1], af[i][2], af[i][3], as + aoff[i] + ks * 32);
                #pragma unroll
                for (int p = 0; p < NLD4; p++) {
                    uint32_t t0, t1, t2, t3;
                    ldsm4(t0, t1, t2, t3, bs + boff4[p] + ks * 32);
                    br0[2 * p] = t0;     br1[2 * p] = t1;
                    br0[2 * p + 1] = t2; br1[2 * p + 1] = t3;
                }
                #pragma unroll
                for (int i = 0; i < MI; i++)
                    #pragma unroll
                    for (int j = 0; j < NJ; j++)
                        mma16816(acc[i][j], af[i][0], af[i][1], af[i][2], af[i][3],
                                 br0[j], br1[j]);
            }
        }
    }

    // ---- epilogue ----
    const int g  = lane >> 2;
    const int cq = (lane & 3) * 2;
    #pragma unroll
    for (int mi = 0; mi < MI; mi++) {
        #pragma unroll
        for (int half = 0; half < 2; half++) {
            const int row = bm + wm * WMT + mi * 16 + half * 8 + g;
            const int h2 = half * 2;

            if (MODE == 1) {
                // fused fc + h: 4-child fcsum/hsum reduction (no early-exit: shfl
                // needs all lanes; child quads align with shfl quads since lcnt%4==0)
                const int rc   = (row < M) ? row : M - 1;
                const int t    = rc / lcnt;
                const int off  = rc % lcnt;
                const bool valid = (row < M) && (off < lvalid);
                const int loc  = lstart + ((off < lvalid) ? off : 0);
                const __half* xrow = xwf + (size_t)(t * NPAR + (loc - 1) / BRANCH) * HH;
                const size_t gnr = (size_t)(t * TT + loc) * HH;
                const __half* crow = cbuf + gnr;
                const __half* hrow = A + gnr;          // A == h16, strideA == HH
                float redf[NJ][2], redh[NJ][2];
                #pragma unroll
                for (int nj = 0; nj < NJ; nj++) {
                    const int col = bn + wn * WNT + nj * 8 + cq;
                    float2 xr = __half22float2(*(const __half2*)(xrow + col));
                    float2 cr = __half22float2(*(const __half2*)(crow + col));
                    float2 hr = __half22float2(*(const __half2*)(hrow + col));
                    float v0 = sigmoid_fast(acc[mi][nj][h2]     + xr.x) * cr.x;
                    float v1 = sigmoid_fast(acc[mi][nj][h2 + 1] + xr.y) * cr.y;
                    float w0 = hr.x, w1 = hr.y;
                    if (!valid) { v0 = 0.f; v1 = 0.f; w0 = 0.f; w1 = 0.f; }
                    v0 += __shfl_xor_sync(0xffffffffu, v0, 4);
                    v0 += __shfl_xor_sync(0xffffffffu, v0, 8);
                    v1 += __shfl_xor_sync(0xffffffffu, v1, 4);
                    v1 += __shfl_xor_sync(0xffffffffu, v1, 8);
                    w0 += __shfl_xor_sync(0xffffffffu, w0, 4);
                    w0 += __shfl_xor_sync(0xffffffffu, w0, 8);
                    w1 += __shfl_xor_sync(0xffffffffu, w1, 4);
                    w1 += __shfl_xor_sync(0xffffffffu, w1, 8);
                    redf[nj][0] = v0; redf[nj][1] = v1;
                    redh[nj][0] = w0; redh[nj][1] = w1;
                }
                if ((lane & 12) == 0 && valid) {
                    const size_t pr = (size_t)(t * pcnt + (off >> 2)) * HH;
                    #pragma unroll
                    for (int nj = 0; nj < NJ; nj++) {
                        const int col = bn + wn * WNT + nj * 8 + cq;
                        *(__half2*)(fcsum_out + pr + col) = __floats2half2_rn(redf[nj][0], redf[nj][1]);
                        *(__half2*)(hsum_out + pr + col) = __floats2half2_rn(redh[nj][0], redh[nj][1]);
                    }
                }
            } else if (MODE == 2) {
                if (row >= M) continue;
                const int t = row / lcnt, loc = lstart + row % lcnt;
                const size_t gn = (size_t)(t * TT + loc) * HH;
                #pragma unroll
                for (int b = 0; b < NJ / 3; b++) {
                    const int hc = blockIdx.x * 32 + wn * 16 + b * 8 + cq;
                    float fs0 = 0.f, fs1 = 0.f;
                    if (fcsum) {
                        float2 f = __half22float2(*(const __half2*)(fcsum + (size_t)row * HH + hc));
                        fs0 = f.x; fs1 = f.y;
                    }
                    float iv0 = acc[mi][b * 3 + 0][h2]     + bias[hc];
                    float iv1 = acc[mi][b * 3 + 0][h2 + 1] + bias[hc + 1];
                    float ov0 = acc[mi][b * 3 + 1][h2]     + bias[HH + hc];
                    float ov1 = acc[mi][b * 3 + 1][h2 + 1] + bias[HH + hc + 1];
                    float uv0 = acc[mi][b * 3 + 2][h2]     + bias[2 * HH + hc];
                    float uv1 = acc[mi][b * 3 + 2][h2 + 1] + bias[2 * HH + hc + 1];
                    float cn0 = sigmoid_fast(iv0) * tanh_fast(uv0) + fs0;
                    float cn1 = sigmoid_fast(iv1) * tanh_fast(uv1) + fs1;
                    float hn0 = sigmoid_fast(ov0) * tanh_fast(cn0);
                    float hn1 = sigmoid_fast(ov1) * tanh_fast(cn1);
                    *(__half2*)(cout + gn + hc)   = __floats2half2_rn(cn0, cn1);
                    *(__half2*)(h16out + gn + hc) = __floats2half2_rn(hn0, hn1);
                }
            } else {
                if (row >= M) continue;
                __half* orow = h16out + (size_t)row * Nw;   // MODE0: fp16 output
                #pragma unroll
                for (int nj = 0; nj < NJ; nj++) {
                    const int col = bn + wn * WNT + nj * 8 + cq;
                    float2 bb = *(const float2*)(bias + col);
                    *(__half2*)(orow + col) =
                        __floats2half2_rn(acc[mi][nj][h2] + bb.x, acc[mi][nj][h2 + 1] + bb.y);
                }
            }
        }
    }
}

// ---------------- fp32 -> fp16 cast (float4-vectorized) ----------------
__global__ void cvt16(const float* __restrict__ in, __half* __restrict__ o, int n4) {
    for (int i = blockIdx.x * blockDim.x + threadIdx.x; i < n4;
         i += gridDim.x * blockDim.x) {
        float4 v = ((const float4*)in)[i];
        __half2 a = __floats2half2_rn(v.x, v.y);
        __half2 b = __floats2half2_rn(v.z, v.w);
        ((__half2*)o)[2 * i]     = a;
        ((__half2*)o)[2 * i + 1] = b;
    }
}

// ---------------- weight transpose + fp16 (+optional gate-interleave permute) --------
template<int PERM>
__global__ void wtrans16(const float* __restrict__ W, __half* __restrict__ Wt,
                         int K, int N)
{
    __shared__ float t[32][33];
    const int bx = blockIdx.x * 32;
    const int by = blockIdx.y * 32;
    const int x = threadIdx.x, y = threadIdx.y;
    #pragma unroll
    for (int i = 0; i < 32; i += 8)
        t[y + i][x] = W[(size_t)(by + y + i) * N + bx + x];
    __syncthreads();
    #pragma unroll
    for (int i = 0; i < 32; i += 8) {
        int n = bx + y + i;
        int np = n;
        if (PERM) {
            int gg = n / HH, Hc = n % HH;
            np = (Hc / 8) * 24 + gg * 8 + (Hc % 8);
        }
        Wt[(size_t)np * K + by + x] = __float2half(t[x][y + i]);
    }
}

// ---------------- zero-fill hsum/fcsum rows for childless level-2 parents ------------
__global__ void tl_zfill(__half* __restrict__ hsum16, __half* __restrict__ fcsum,
                         int B, int Poff, int Pcnt, int Pfill)
{
    int total = B * Pfill * HH;
    for (int idx = blockIdx.x * blockDim.x + threadIdx.x; idx < total;
         idx += gridDim.x * blockDim.x) {
        int n = idx & (HH - 1);
        int pr = idx >> 9;
        int t = pr / Pfill;
        int p = Poff + pr % Pfill;
        size_t a = (size_t)(t * Pcnt + p) * HH + n;
        hsum16[a] = __float2half(0.f);
        fcsum[a]  = __float2half(0.f);
    }
}

// ---------------- readout (half2-vectorized; accurate tanh on output) ----------------
__global__ void tl_readout(const __half* __restrict__ h16, float* __restrict__ out, int B)
{
    const int g = blockIdx.x;
    const int n2 = threadIdx.x;                    // 0..255 -> cols 2*n2, 2*n2+1
    const __half2* hp = (const __half2*)(h16 + (size_t)g * TT * HH) + n2;
    float s0 = 0.f, s1 = 0.f;
    #pragma unroll
    for (int tn = 0; tn < TT; tn++) {
        float2 v = __half22float2(hp[(size_t)tn * (HH / 2)]);
        s0 += v.x; s1 += v.y;
    }
    const int n = 2 * n2;
    if (n < 256) {
        out[(size_t)g * 256 + n]     = s0;
        out[(size_t)g * 256 + n + 1] = s1;
    } else {
        out[(size_t)B * 256 + (size_t)g * 256 + (n - 256)]     = tanhf(s0);
        out[(size_t)B * 256 + (size_t)g * 256 + (n - 256) + 1] = tanhf(s1);
    }
}

// ---------------- launch ----------------
extern "C" void kernel_launch(void* const* d_in, const int* in_sizes, int n_in,
                              void* d_out, int out_size)
{
    const float* embed = (const float*)d_in[0];
    const float* W_iou = (const float*)d_in[1];
    const float* U_iou = (const float*)d_in[2];
    const float* b_iou = (const float*)d_in[3];
    const float* W_f   = (const float*)d_in[4];
    const float* U_f   = (const float*)d_in[5];
    const float* b_f   = (const float*)d_in[6];

    int N = in_sizes[0] / D_IN;
    int B = N / TT;
    if (B > MAXB) B = MAXB;

    __half *c, *xwf, *fcsum, *e16, *h16, *hsum16, *Wt_iou, *Ut_iou, *Wt_f, *Ut_f;
    cudaGetSymbolAddress((void**)&c,      g_c);
    cudaGetSymbolAddress((void**)&xwf,    g_xwf);
    cudaGetSymbolAddress((void**)&fcsum,  g_fcsum);
    cudaGetSymbolAddress((void**)&e16,    g_e16);
    cudaGetSymbolAddress((void**)&h16,    g_h16);
    cudaGetSymbolAddress((void**)&hsum16, g_hsum16);
    cudaGetSymbolAddress((void**)&Wt_iou, g_Wt_iou);
    cudaGetSymbolAddress((void**)&Ut_iou, g_Ut_iou);
    cudaGetSymbolAddress((void**)&Wt_f,   g_Wt_f);
    cudaGetSymbolAddress((void**)&Ut_f,   g_Ut_f);

    const int SM01 = 4 * (128 * ROWB + 128 * ROWB);   // 81920  (2 CTAs/SM)
    const int SM2  = 5 * (128 * ROWB + 96 * ROWB);    // 89600  (2 CTAs/SM)
    cudaFuncSetAttribute(hgemm<0>, cudaFuncAttributeMaxDynamicSharedMemorySize, SM01);
    cudaFuncSetAttribute(hgemm<1>, cudaFuncAttributeMaxDynamicSharedMemorySize, SM01);
    cudaFuncSetAttribute(hgemm<2>, cudaFuncAttributeMaxDynamicSharedMemorySize, SM2);

    dim3 tb(32, 8);
    cvt16<<<4096, 256>>>(embed, e16, B * TT * D_IN / 4);                       // 1
    wtrans16<1><<<dim3(G3 / 32, D_IN / 32), tb>>>(W_iou, Wt_iou, D_IN, G3);    // 2
    wtrans16<0><<<dim3(HH / 32, D_IN / 32), tb>>>(W_f,   Wt_f,   D_IN, HH);    // 3

    #define GY(M) (((M) + 127) / 128)

    // 4: level 3 (deepest): fused gates+cell, no children  [ncu sample target]
    hgemm<2><<<dim3(G3 / 96, GY(B * 29)), 256, SM2>>>(
        e16, Wt_iou, D_IN, D_IN, nullptr, nullptr, 0,
        b_iou, nullptr, nullptr, c, h16, nullptr, nullptr, nullptr,
        B * 29, G3, 21, 29, 29, 0);

    // 5: xwf (fp16) for parent-capable nodes (locals 0..12)
    hgemm<0><<<dim3(HH / 128, GY(B * NPAR)), 256, SM01>>>(
        e16, Wt_f, D_IN, D_IN, nullptr, nullptr, 0,
        b_f, nullptr, nullptr, nullptr, xwf, nullptr, nullptr, nullptr,
        B * NPAR, HH, 0, NPAR, NPAR, 0);

    wtrans16<1><<<dim3(G3 / 32, HH / 32), tb>>>(U_iou, Ut_iou, HH, G3);        // 6
    wtrans16<0><<<dim3(HH / 32, HH / 32), tb>>>(U_f,   Ut_f,   HH, HH);        // 7

    // zero hsum/fcsum for level-2 childless parents (locals 13..20 -> offs 8..15)
    tl_zfill<<<512, 256>>>(hsum16, fcsum, B, 8, 16, 8);                        // 8

    // {Pstart, Pcnt, Cstart, CcntPad, CcntValid}
    const int lp[3][5] = { {5, 16, 21, 32, 29}, {1, 4, 5, 16, 16}, {0, 1, 1, 4, 4} };
    for (int li = 0; li < 3; li++) {
        int Pstart = lp[li][0], Pcnt = lp[li][1], Cstart = lp[li][2];
        int Cpad = lp[li][3], Cval = lp[li][4];

        // fc = sigmoid(h_child @ U_f + xwf[parent]) * c_child;
        // fcsum (fp16) + hsum (fp16) fused via shfl over the 4-child quad
        hgemm<1><<<dim3(HH / 128, GY(B * Cpad)), 256, SM01>>>(
            h16, Ut_f, HH, HH, nullptr, nullptr, 0,
            nullptr, xwf, c, nullptr, nullptr, nullptr, fcsum, hsum16,
            B * Cpad, HH, Cstart, Cpad, Cval, Pcnt);

        // fused: gates = E@W_iou + hsum@U_iou + b  ->  cell  -> h16, c
        hgemm<2><<<dim3(G3 / 96, GY(B * Pcnt)), 256, SM2>>>(
            e16, Wt_iou, D_IN, D_IN, hsum16, Ut_iou, HH,
            b_iou, nullptr, nullptr, c, h16, fcsum, nullptr, nullptr,
            B * Pcnt, G3, Pstart, Pcnt, Pcnt, 0);
    }

    tl_readout<<<B, 256>>>(h16, (float*)d_out, B);
    #undef GY
}

// round 17
// speedup vs baseline: 1.0335x; 1.0095x over previous
#include <cuda_runtime.h>
#include <cuda_fp16.h>
#include <cstdint>
#include <math.h>

// ---------------- fixed problem structure ----------------
#define TT      50
#define BRANCH  4
#define D_IN    384
#define HH      512
#define G3      1536
#define MAXB    2000
#define NPAR    13
#define NNODE   (MAXB * TT)

// ---------------- device scratch ----------------
__device__ __half g_c    [(size_t)NNODE * HH];
__device__ __half g_xwf  [(size_t)MAXB * NPAR * HH];
__device__ __half g_fcsum[(size_t)MAXB * 16 * HH];
__device__ __half g_e16  [(size_t)NNODE * D_IN];
__device__ __half g_h16  [(size_t)NNODE * HH];
__device__ __half g_hsum16[(size_t)MAXB * 16 * HH];
__device__ __half g_Wt_iou[G3 * D_IN];   // fp16, K-major [N'][K], gate-interleaved N'
__device__ __half g_Ut_iou[G3 * HH];     // gate-interleaved N'
__device__ __half g_Wt_f  [HH * D_IN];
__device__ __half g_Ut_f  [HH * HH];

// ---------------- PTX helpers (portable ISA: sm_80-level) ----------------
__device__ __forceinline__ uint32_t s2u(const void* p) {
    uint32_t a;
    asm("{ .reg .u64 t; cvta.to.shared.u64 t, %1; cvt.u32.u64 %0, t; }" : "=r"(a) : "l"(p));
    return a;
}
__device__ __forceinline__ void cpasync16(uint32_t dst, const void* src) {
    asm volatile("cp.async.cg.shared.global [%0], [%1], 16;" :: "r"(dst), "l"(src));
}
__device__ __forceinline__ void cpcommit() {
    asm volatile("cp.async.commit_group;" ::: "memory");
}
template<int N>
__device__ __forceinline__ void cpwait() {
    asm volatile("cp.async.wait_group %0;" :: "n"(N) : "memory");
}
__device__ __forceinline__ void ldsm4(uint32_t& r0, uint32_t& r1, uint32_t& r2, uint32_t& r3,
                                      uint32_t a) {
    asm volatile("ldmatrix.sync.aligned.m8n8.x4.shared.b16 {%0,%1,%2,%3}, [%4];"
                 : "=r"(r0), "=r"(r1), "=r"(r2), "=r"(r3) : "r"(a));
}
__device__ __forceinline__ void mma16816(float* c,
                                         uint32_t a0, uint32_t a1, uint32_t a2, uint32_t a3,
                                         uint32_t b0, uint32_t b1) {
    asm volatile(
        "mma.sync.aligned.m16n8k16.row.col.f32.f16.f16.f32 "
        "{%0,%1,%2,%3}, {%4,%5,%6,%7}, {%8,%9}, {%0,%1,%2,%3};"
        : "+f"(c[0]), "+f"(c[1]), "+f"(c[2]), "+f"(c[3])
        : "r"(a0), "r"(a1), "r"(a2), "r"(a3), "r"(b0), "r"(b1));
}
__device__ __forceinline__ float tanh_fast(float x) {
    float r;
    asm("tanh.approx.f32 %0, %1;" : "=f"(r) : "f"(x));
    return r;
}
__device__ __forceinline__ float sigmoid_fast(float x) {
    return fmaf(tanh_fast(0.5f * x), 0.5f, 0.5f);
}

// ---------------- GEMM tiling ----------------
#define BK     32                      // halves per k-chunk
#define ROWB   80                      // smem row stride (bytes)

// MODE 0: xwf16 = acc + bias (fp16 out)                    (128x128, warps 2x4, 4 stg)
// MODE 1: fc = sigmoid(acc + xwf16[parent]) * c[child];
//         fcsum + hsum over 4 children via shfl            (128x128, warps 2x4, 4 stg)
// MODE 2: fused LSTM cell, gate-interleaved cols           (128x96, warps 4x2, 32x48, 5 stg)
template<int MODE>
__global__ void __launch_bounds__(256, 2)
hgemm(const __half* __restrict__ A,  const __half* __restrict__ B1, int K1, int strideA,
      const __half* __restrict__ A2, const __half* __restrict__ B2, int K2,
      const float* __restrict__ bias, const __half* __restrict__ xwf,
      const __half* __restrict__ cbuf,
      __half* __restrict__ cout, __half* __restrict__ h16out,
      const __half* __restrict__ fcsum, __half* __restrict__ fcsum_out,
      __half* __restrict__ hsum_out,
      int M, int Nw, int lstart, int lcnt, int lvalid, int pcnt)
{
    constexpr int THREADS = 256;
    constexpr int ST   = (MODE == 2) ? 5 : 4;     // pipeline stages
    constexpr int MT   = 128;
    constexpr int NT   = (MODE == 2) ? 96 : 128;
    constexpr int WMW  = (MODE == 2) ? 4 : 2;     // warps along M
    constexpr int WMT  = MT / WMW;                // 32 / 64
    constexpr int WNT  = NT / (8 / WMW);          // 48 / 32
    constexpr int MI   = WMT / 16;                // 2 / 4
    constexpr int NJ   = WNT / 8;                 // 6 / 4
    constexpr int NLD4 = WNT / 16;                // 3 / 2
    constexpr int ASTG = MT * ROWB;
    constexpr int BSTG = NT * ROWB;
    constexpr int NBL  = (NT * 4 + THREADS - 1) / THREADS;

    extern __shared__ char smraw[];
    const uint32_t sb  = s2u(smraw);
    const uint32_t sbB = sb + ST * ASTG;

    const int tid  = threadIdx.x;
    const int lane = tid & 31;
    const int wid  = tid >> 5;
    const int wm   = (MODE == 2) ? (wid >> 1) : (wid >> 2);
    const int wn   = (MODE == 2) ? (wid & 1)  : (wid & 3);
    const int bm   = blockIdx.y * MT;
    const int bn   = blockIdx.x * NT;

    // ---- A loader: 2 gathered (row, 16B-chunk) slots per thread ----
    const __half* a1p[2];
    const __half* a2p[2];
    uint32_t asf[2];
    #pragma unroll
    for (int t = 0; t < 2; t++) {
        const int idx = tid + t * THREADS;
        int r = bm + (idx >> 2); if (r >= M) r = M - 1;
        int o = r % lcnt; if (o >= lvalid) o = lvalid - 1;
        const int tr = r / lcnt, lc = lstart + o;
        const int ch = idx & 3;
        a1p[t] = A + (size_t)(tr * TT + lc) * strideA + ch * 8;
        a2p[t] = (K2 > 0) ? A2 + (size_t)r * K2 + ch * 8 : nullptr;
        asf[t] = (uint32_t)((idx >> 2) * ROWB + ch * 16);
    }

    // ---- B loader ----
    const __half* pb1[NBL];
    const __half* pb2[NBL];
    uint32_t bso[NBL];
    bool bok[NBL];
    #pragma unroll
    for (int i = 0; i < NBL; i++) {
        const int idx = tid + i * THREADS;
        bok[i] = idx < NT * 4;
        const int row = bok[i] ? (idx >> 2) : 0;
        const int ch  = idx & 3;
        pb1[i] = B1 + (size_t)(bn + row) * K1 + ch * 8;
        pb2[i] = (K2 > 0) ? B2 + (size_t)(bn + row) * K2 + ch * 8 : nullptr;
        bso[i] = (uint32_t)(row * ROWB + ch * 16);
    }

    const int n1 = K1 / BK, n2 = (K2 > 0) ? K2 / BK : 0, nt = n1 + n2;

    auto issue = [&](int ci, int s) {
        const bool p2 = (ci >= n1);
        const int  kb = (p2 ? (ci - n1) : ci) * BK;
        const uint32_t abase = sb  + s * ASTG;
        const uint32_t bbase = sbB + s * BSTG;
        #pragma unroll
        for (int t = 0; t < 2; t++)
            cpasync16(abase + asf[t], (p2 ? a2p[t] : a1p[t]) + kb);
        #pragma unroll
        for (int i = 0; i < NBL; i++)
            if (bok[i]) cpasync16(bbase + bso[i], (p2 ? pb2[i] : pb1[i]) + kb);
    };

    // ---- ldmatrix offsets ----
    const int rl = (lane & 7) + ((lane >> 3) & 1) * 8;
    const int kq = (lane >> 4) * 16;
    uint32_t aoff[MI];
    #pragma unroll
    for (int i = 0; i < MI; i++)
        aoff[i] = (uint32_t)((wm * WMT + i * 16 + rl) * ROWB + kq);
    const int nl  = (lane & 7) + (lane >> 4) * 8;
    const int kb2 = ((lane >> 3) & 1) * 16;
    uint32_t boff4[NLD4];
    #pragma unroll
    for (int p = 0; p < NLD4; p++)
        boff4[p] = (uint32_t)((wn * WNT + p * 16 + nl) * ROWB + kb2);

    float acc[MI][NJ][4];
    #pragma unroll
    for (int i = 0; i < MI; i++)
        #pragma unroll
        for (int j = 0; j < NJ; j++)
            #pragma unroll
            for (int q = 0; q < 4; q++) acc[i][j][q] = 0.f;

    #pragma unroll
    for (int s = 0; s < ST - 1; s++) { issue(s, s); cpcommit(); }

    if constexpr (MODE == 2) {
        // ---- software-pipelined fragments: double-buffered regs ----
        uint32_t af[2][MI][4], b0f[2][NJ], b1f[2][NJ];
        auto lf = [&](int buf, uint32_t as, uint32_t bs, int ks) {
            #pragma unroll
            for (int i = 0; i < MI; i++)
                ldsm4(af[buf][i][0], af[buf][i][1], af[buf][i][2], af[buf][i][3],
                      as + aoff[i] + ks * 32);
            #pragma unroll
            for (int p = 0; p < NLD4; p++) {
                uint32_t t0, t1, t2, t3;
                ldsm4(t0, t1, t2, t3, bs + boff4[p] + ks * 32);
                b0f[buf][2 * p] = t0;     b1f[buf][2 * p] = t1;
                b0f[buf][2 * p + 1] = t2; b1f[buf][2 * p + 1] = t3;
            }
        };
        auto mm = [&](int buf) {
            #pragma unroll
            for (int i = 0; i < MI; i++)
                #pragma unroll
                for (int j = 0; j < NJ; j++)
                    mma16816(acc[i][j], af[buf][i][0], af[buf][i][1],
                             af[buf][i][2], af[buf][i][3], b0f[buf][j], b1f[buf][j]);
        };

        cpwait<ST - 2>();
        __syncthreads();
        lf(0, sb, sbB, 0);

        for (int ci = 0; ci < nt; ci++) {
            const uint32_t as = sb  + (ci % ST) * ASTG;
            const uint32_t bs = sbB + (ci % ST) * BSTG;
            const int pre = ci + ST - 1;
            if (pre < nt) issue(pre, pre % ST);
            cpcommit();
            lf(1, as, bs, 1);          // ks=1 frags load behind ks=0 MMAs
            mm(0);
            cpwait<ST - 2>();          // chunk ci+1 stage complete
            __syncthreads();
            if (ci + 1 < nt)
                lf(0, sb + ((ci + 1) % ST) * ASTG,
                       sbB + ((ci + 1) % ST) * BSTG, 0);
            mm(1);
        }
    } else {
        for (int ci = 0; ci < nt; ci++) {
            cpwait<ST - 2>();
            __syncthreads();

            const int pre = ci + ST - 1;
            if (pre < nt) issue(pre, pre % ST);
            cpcommit();

            const uint32_t as = sb  + (ci % ST) * ASTG;
            const uint32_t bs = sbB + (ci % ST) * BSTG;

            #pragma unroll
            for (int ks = 0; ks < 2; ks++) {
                uint32_t af[MI][4];
                uint32_t br0[NJ], br1[NJ];
                #pragma unroll
                for (int i = 0; i < MI; i++)
                    ldsm4(af[i][0], af[i][1], af[i][2], af[i][3], as + aoff[i] + ks * 32);
                #pragma unroll
                for (int p = 0; p < NLD4; p++) {
                    uint32_t t0, t1, t2, t3;
                    ldsm4(t0, t1, t2, t3, bs + boff4[p] + ks * 32);
                    br0[2 * p] = t0;     br1[2 * p] = t1;
                    br0[2 * p + 1] = t2; br1[2 * p + 1] = t3;
                }
                #pragma unroll
                for (int i = 0; i < MI; i++)
                    #pragma unroll
                    for (int j = 0; j < NJ; j++)
                        mma16816(acc[i][j], af[i][0], af[i][1], af[i][2], af[i][3],
                                 br0[j], br1[j]);
            }
        }
    }

    // ---- epilogue ----
    const int g  = lane >> 2;
    const int cq = (lane & 3) * 2;
    #pragma unroll
    for (int mi = 0; mi < MI; mi++) {
        #pragma unroll
        for (int half = 0; half < 2; half++) {
            const int row = bm + wm * WMT + mi * 16 + half * 8 + g;
            const int h2 = half * 2;

            if (MODE == 1) {
                // fused fc + h: 4-child fcsum/hsum reduction (no early-exit: shfl
                // needs all lanes; child quads align with shfl quads since lcnt%4==0)
                const int rc   = (row < M) ? row : M - 1;
                const int t    = rc / lcnt;
                const int off  = rc % lcnt;
                const bool valid = (row < M) && (off < lvalid);
                const int loc  = lstart + ((off < lvalid) ? off : 0);
                const __half* xrow = xwf + (size_t)(t * NPAR + (loc - 1) / BRANCH) * HH;
                const size_t gnr = (size_t)(t * TT + loc) * HH;
                const __half* crow = cbuf + gnr;
                const __half* hrow = A + gnr;          // A == h16, strideA == HH
                float redf[NJ][2], redh[NJ][2];
                #pragma unroll
                for (int nj = 0; nj < NJ; nj++) {
                    const int col = bn + wn * WNT + nj * 8 + cq;
                    float2 xr = __half22float2(*(const __half2*)(xrow + col));
                    float2 cr = __half22float2(*(const __half2*)(crow + col));
                    float2 hr = __half22float2(*(const __half2*)(hrow + col));
                    float v0 = sigmoid_fast(acc[mi][nj][h2]     + xr.x) * cr.x;
                    float v1 = sigmoid_fast(acc[mi][nj][h2 + 1] + xr.y) * cr.y;
                    float w0 = hr.x, w1 = hr.y;
                    if (!valid) { v0 = 0.f; v1 = 0.f; w0 = 0.f; w1 = 0.f; }
                    v0 += __shfl_xor_sync(0xffffffffu, v0, 4);
                    v0 += __shfl_xor_sync(0xffffffffu, v0, 8);
                    v1 += __shfl_xor_sync(0xffffffffu, v1, 4);
                    v1 += __shfl_xor_sync(0xffffffffu, v1, 8);
                    w0 += __shfl_xor_sync(0xffffffffu, w0, 4);
                    w0 += __shfl_xor_sync(0xffffffffu, w0, 8);
                    w1 += __shfl_xor_sync(0xffffffffu, w1, 4);
                    w1 += __shfl_xor_sync(0xffffffffu, w1, 8);
                    redf[nj][0] = v0; redf[nj][1] = v1;
                    redh[nj][0] = w0; redh[nj][1] = w1;
                }
                if ((lane & 12) == 0 && valid) {
                    const size_t pr = (size_t)(t * pcnt + (off >> 2)) * HH;
                    #pragma unroll
                    for (int nj = 0; nj < NJ; nj++) {
                        const int col = bn + wn * WNT + nj * 8 + cq;
                        *(__half2*)(fcsum_out + pr + col) = __floats2half2_rn(redf[nj][0], redf[nj][1]);
                        *(__half2*)(hsum_out + pr + col) = __floats2half2_rn(redh[nj][0], redh[nj][1]);
                    }
                }
            } else if (MODE == 2) {
                if (row >= M) continue;
                const int t = row / lcnt, loc = lstart + row % lcnt;
                const size_t gn = (size_t)(t * TT + loc) * HH;
                #pragma unroll
                for (int b = 0; b < NJ / 3; b++) {
                    const int hc = blockIdx.x * 32 + wn * 16 + b * 8 + cq;
                    float fs0 = 0.f, fs1 = 0.f;
                    if (fcsum) {
                        float2 f = __half22float2(*(const __half2*)(fcsum + (size_t)row * HH + hc));
                        fs0 = f.x; fs1 = f.y;
                    }
                    float iv0 = acc[mi][b * 3 + 0][h2]     + bias[hc];
                    float iv1 = acc[mi][b * 3 + 0][h2 + 1] + bias[hc + 1];
                    float ov0 = acc[mi][b * 3 + 1][h2]     + bias[HH + hc];
                    float ov1 = acc[mi][b * 3 + 1][h2 + 1] + bias[HH + hc + 1];
                    float uv0 = acc[mi][b * 3 + 2][h2]     + bias[2 * HH + hc];
                    float uv1 = acc[mi][b * 3 + 2][h2 + 1] + bias[2 * HH + hc + 1];
                    float cn0 = sigmoid_fast(iv0) * tanh_fast(uv0) + fs0;
                    float cn1 = sigmoid_fast(iv1) * tanh_fast(uv1) + fs1;
                    float hn0 = sigmoid_fast(ov0) * tanh_fast(cn0);
                    float hn1 = sigmoid_fast(ov1) * tanh_fast(cn1);
                    *(__half2*)(cout + gn + hc)   = __floats2half2_rn(cn0, cn1);
                    *(__half2*)(h16out + gn + hc) = __floats2half2_rn(hn0, hn1);
                }
            } else {
                if (row >= M) continue;
                __half* orow = h16out + (size_t)row * Nw;   // MODE0: fp16 output
                #pragma unroll
                for (int nj = 0; nj < NJ; nj++) {
                    const int col = bn + wn * WNT + nj * 8 + cq;
                    float2 bb = *(const float2*)(bias + col);
                    *(__half2*)(orow + col) =
                        __floats2half2_rn(acc[mi][nj][h2] + bb.x, acc[mi][nj][h2 + 1] + bb.y);
                }
            }
        }
    }
}

// ---------------- fp32 -> fp16 cast (float4-vectorized) ----------------
__global__ void cvt16(const float* __restrict__ in, __half* __restrict__ o, int n4) {
    for (int i = blockIdx.x * blockDim.x + threadIdx.x; i < n4;
         i += gridDim.x * blockDim.x) {
        float4 v = ((const float4*)in)[i];
        __half2 a = __floats2half2_rn(v.x, v.y);
        __half2 b = __floats2half2_rn(v.z, v.w);
        ((__half2*)o)[2 * i]     = a;
        ((__half2*)o)[2 * i + 1] = b;
    }
}

// ---------------- all four weight transposes in ONE launch ----------------
// tiles: Wiou 576 (48x12, perm), Uiou 768 (48x16, perm), Wf 192 (16x12), Uf 256 (16x16)
__global__ void wtrans_all(const float* __restrict__ W_iou, const float* __restrict__ U_iou,
                           const float* __restrict__ W_f,   const float* __restrict__ U_f,
                           __half* __restrict__ Wt_iou, __half* __restrict__ Ut_iou,
                           __half* __restrict__ Wt_f,   __half* __restrict__ Ut_f)
{
    __shared__ float t[32][33];
    int b = blockIdx.x;
    const float* W; __half* Wt; int K, N, perm, nx;
    if (b < 576)        {          W = W_iou; Wt = Wt_iou; K = D_IN; N = G3; perm = 1; nx = 48; }
    else if (b < 1344)  { b -= 576;  W = U_iou; Wt = Ut_iou; K = HH;   N = G3; perm = 1; nx = 48; }
    else if (b < 1536)  { b -= 1344; W = W_f;   Wt = Wt_f;   K = D_IN; N = HH; perm = 0; nx = 16; }
    else                { b -= 1536; W = U_f;   Wt = Ut_f;   K = HH;   N = HH; perm = 0; nx = 16; }
    const int bx = (b % nx) * 32;
    const int by = (b / nx) * 32;
    const int x = threadIdx.x, y = threadIdx.y;
    #pragma unroll
    for (int i = 0; i < 32; i += 8)
        t[y + i][x] = W[(size_t)(by + y + i) * N + bx + x];
    __syncthreads();
    #pragma unroll
    for (int i = 0; i < 32; i += 8) {
        int n = bx + y + i;
        int np = n;
        if (perm) {
            int gg = n / HH, Hc = n % HH;
            np = (Hc / 8) * 24 + gg * 8 + (Hc % 8);
        }
        Wt[(size_t)np * K + by + x] = __float2half(t[x][y + i]);
    }
}

// ---------------- zero-fill hsum/fcsum rows for childless level-2 parents ------------
__global__ void tl_zfill(__half* __restrict__ hsum16, __half* __restrict__ fcsum,
                         int B, int Poff, int Pcnt, int Pfill)
{
    int total = B * Pfill * (HH / 2);           // half2 granules
    for (int idx = blockIdx.x * blockDim.x + threadIdx.x; idx < total;
         idx += gridDim.x * blockDim.x) {
        int n2 = idx & (HH / 2 - 1);
        int pr = idx >> 8;
        int t = pr / Pfill;
        int p = Poff + pr % Pfill;
        size_t a = (size_t)(t * Pcnt + p) * (HH / 2) + n2;
        ((uint32_t*)hsum16)[a] = 0u;
        ((uint32_t*)fcsum)[a]  = 0u;
    }
}

// ---------------- readout (half2-vectorized; accurate tanh on output) ----------------
__global__ void tl_readout(const __half* __restrict__ h16, float* __restrict__ out, int B)
{
    const int g = blockIdx.x;
    const int n2 = threadIdx.x;                    // 0..255 -> cols 2*n2, 2*n2+1
    const __half2* hp = (const __half2*)(h16 + (size_t)g * TT * HH) + n2;
    float s0 = 0.f, s1 = 0.f;
    #pragma unroll
    for (int tn = 0; tn < TT; tn++) {
        float2 v = __half22float2(hp[(size_t)tn * (HH / 2)]);
        s0 += v.x; s1 += v.y;
    }
    const int n = 2 * n2;
    if (n < 256) {
        out[(size_t)g * 256 + n]     = s0;
        out[(size_t)g * 256 + n + 1] = s1;
    } else {
        out[(size_t)B * 256 + (size_t)g * 256 + (n - 256)]     = tanhf(s0);
        out[(size_t)B * 256 + (size_t)g * 256 + (n - 256) + 1] = tanhf(s1);
    }
}

// ---------------- launch ----------------
extern "C" void kernel_launch(void* const* d_in, const int* in_sizes, int n_in,
                              void* d_out, int out_size)
{
    const float* embed = (const float*)d_in[0];
    const float* W_iou = (const float*)d_in[1];
    const float* U_iou = (const float*)d_in[2];
    const float* b_iou = (const float*)d_in[3];
    const float* W_f   = (const float*)d_in[4];
    const float* U_f   = (const float*)d_in[5];
    const float* b_f   = (const float*)d_in[6];

    int N = in_sizes[0] / D_IN;
    int B = N / TT;
    if (B > MAXB) B = MAXB;

    __half *c, *xwf, *fcsum, *e16, *h16, *hsum16, *Wt_iou, *Ut_iou, *Wt_f, *Ut_f;
    cudaGetSymbolAddress((void**)&c,      g_c);
    cudaGetSymbolAddress((void**)&xwf,    g_xwf);
    cudaGetSymbolAddress((void**)&fcsum,  g_fcsum);
    cudaGetSymbolAddress((void**)&e16,    g_e16);
    cudaGetSymbolAddress((void**)&h16,    g_h16);
    cudaGetSymbolAddress((void**)&hsum16, g_hsum16);
    cudaGetSymbolAddress((void**)&Wt_iou, g_Wt_iou);
    cudaGetSymbolAddress((void**)&Ut_iou, g_Ut_iou);
    cudaGetSymbolAddress((void**)&Wt_f,   g_Wt_f);
    cudaGetSymbolAddress((void**)&Ut_f,   g_Ut_f);

    const int SM01 = 4 * (128 * ROWB + 128 * ROWB);   // 81920  (2 CTAs/SM)
    const int SM2  = 5 * (128 * ROWB + 96 * ROWB);    // 89600  (2 CTAs/SM)
    cudaFuncSetAttribute(hgemm<0>, cudaFuncAttributeMaxDynamicSharedMemorySize, SM01);
    cudaFuncSetAttribute(hgemm<1>, cudaFuncAttributeMaxDynamicSharedMemorySize, SM01);
    cudaFuncSetAttribute(hgemm<2>, cudaFuncAttributeMaxDynamicSharedMemorySize, SM2);

    cvt16<<<4096, 256>>>(embed, e16, B * TT * D_IN / 4);                       // 1
    wtrans_all<<<1792, dim3(32, 8)>>>(W_iou, U_iou, W_f, U_f,                  // 2
                                      Wt_iou, Ut_iou, Wt_f, Ut_f);
    tl_zfill<<<256, 256>>>(hsum16, fcsum, B, 8, 16, 8);                        // 3

    #define GY(M) (((M) + 127) / 128)

    // 4: level 3 (deepest): fused gates+cell, no children  [ncu sample target]
    hgemm<2><<<dim3(G3 / 96, GY(B * 29)), 256, SM2>>>(
        e16, Wt_iou, D_IN, D_IN, nullptr, nullptr, 0,
        b_iou, nullptr, nullptr, c, h16, nullptr, nullptr, nullptr,
        B * 29, G3, 21, 29, 29, 0);

    // 5: xwf (fp16) for parent-capable nodes (locals 0..12)
    hgemm<0><<<dim3(HH / 128, GY(B * NPAR)), 256, SM01>>>(
        e16, Wt_f, D_IN, D_IN, nullptr, nullptr, 0,
        b_f, nullptr, nullptr, nullptr, xwf, nullptr, nullptr, nullptr,
        B * NPAR, HH, 0, NPAR, NPAR, 0);

    // {Pstart, Pcnt, Cstart, CcntPad, CcntValid}
    const int lp[3][5] = { {5, 16, 21, 32, 29}, {1, 4, 5, 16, 16}, {0, 1, 1, 4, 4} };
    for (int li = 0; li < 3; li++) {
        int Pstart = lp[li][0], Pcnt = lp[li][1], Cstart = lp[li][2];
        int Cpad = lp[li][3], Cval = lp[li][4];

        // fc = sigmoid(h_child @ U_f + xwf[parent]) * c_child;
        // fcsum (fp16) + hsum (fp16) fused via shfl over the 4-child quad
        hgemm<1><<<dim3(HH / 128, GY(B * Cpad)), 256, SM01>>>(
            h16, Ut_f, HH, HH, nullptr, nullptr, 0,
            nullptr, xwf, c, nullptr, nullptr, nullptr, fcsum, hsum16,
            B * Cpad, HH, Cstart, Cpad, Cval, Pcnt);

        // fused: gates = E@W_iou + hsum@U_iou + b  ->  cell  -> h16, c
        hgemm<2><<<dim3(G3 / 96, GY(B * Pcnt)), 256, SM2>>>(
            e16, Wt_iou, D_IN, D_IN, hsum16, Ut_iou, HH,
            b_iou, nullptr, nullptr, c, h16, fcsum, nullptr, nullptr,
            B * Pcnt, G3, Pstart, Pcnt, Pcnt, 0);
    }

    tl_readout<<<B, 256>>>(h16, (float*)d_out, B);
    #undef GY
}